// round 1
// baseline (speedup 1.0000x reference)
#include <cuda_runtime.h>
#include <math.h>

#define N_TOK   4096
#define CDIM    256
#define HID     128
#define NHEADS  4
#define DHEAD   32
#define QKV_M   384
#define TDIM    512
#define QSCALE  0.17677669529663687f   // 32^-0.5

// ---------------- scratch (static device globals; no allocation) -------------
__device__ float g_s1[2 * CDIM];        // scale + 1
__device__ float g_shift[2 * CDIM];
__device__ float g_biasqkv[2 * QKV_M];  // sum_c w_qkv[o,c] * shift[b,c]
__device__ float g_q[8 * N_TOK * DHEAD];   // [bh][n][d], pre-scaled
__device__ float g_k[8 * N_TOK * DHEAD];   // [bh][n][d]
__device__ float g_v[8 * N_TOK * DHEAD];   // [bh][n][d]
__device__ float g_ao[2 * HID * N_TOK];    // attention out [b][h*32+d][n]

// ---------------- 1) FiLM MLP: t = silu(te) @ w_mlp^T + b_mlp ---------------
__global__ void film_kernel(const float* __restrict__ te,
                            const float* __restrict__ w_mlp,
                            const float* __restrict__ b_mlp) {
    int gw   = (blockIdx.x * blockDim.x + threadIdx.x) >> 5;  // global warp
    int lane = threadIdx.x & 31;
    if (gw >= 2 * 2 * CDIM) return;            // 1024 warps
    int b = gw / (2 * CDIM);
    int j = gw % (2 * CDIM);
    const float* e = te + b * TDIM;
    const float* wr = w_mlp + (size_t)j * TDIM;
    float s = 0.f;
    for (int i = lane; i < TDIM; i += 32) {
        float x  = e[i];
        float si = x / (1.f + __expf(-x));
        s += si * wr[i];
    }
#pragma unroll
    for (int o = 16; o; o >>= 1) s += __shfl_xor_sync(0xffffffffu, s, o);
    if (lane == 0) {
        float t = s + b_mlp[j];
        if (j < CDIM) g_s1[b * CDIM + j] = t + 1.f;
        else          g_shift[b * CDIM + (j - CDIM)] = t;
    }
}

// ---------------- 2) bias_qkv[b][o] = sum_c w_qkv[o,c] * shift[b,c] ----------
__global__ void biasqkv_kernel(const float* __restrict__ w_qkv) {
    int gw   = (blockIdx.x * blockDim.x + threadIdx.x) >> 5;
    int lane = threadIdx.x & 31;
    if (gw >= 2 * QKV_M) return;               // 768 warps
    int b = gw / QKV_M;
    int o = gw % QKV_M;
    const float* wr = w_qkv + (size_t)o * CDIM;
    const float* sh = g_shift + b * CDIM;
    float s = 0.f;
    for (int c = lane; c < CDIM; c += 32) s += wr[c] * sh[c];
#pragma unroll
    for (int off = 16; off; off >>= 1) s += __shfl_xor_sync(0xffffffffu, s, off);
    if (lane == 0) g_biasqkv[b * QKV_M + o] = s;
}

// ---------------- 3) QKV GEMM (FiLM folded in) --------------------------------
// qkv[b,o,n] = sum_c (w_qkv[o,c]*s1[b,c]) * x[b,c,n] + bias_qkv[b,o]
// 64x64 tile, K-chunks of 16, thread = 4x4 micro-tile.
__global__ void qkv_gemm(const float* __restrict__ x,
                         const float* __restrict__ w_qkv) {
    __shared__ float As[16][68];  // A^T: As[c][o]
    __shared__ float Bs[16][68];  // Bs[c][n]
    const int b  = blockIdx.z;
    const int o0 = blockIdx.y * 64;
    const int n0 = blockIdx.x * 64;
    const int tid = threadIdx.x;
    const int tx = tid & 15, ty = tid >> 4;

    float acc[4][4] = {};
    const float* s1 = g_s1 + b * CDIM;
    for (int cb = 0; cb < CDIM; cb += 16) {
#pragma unroll
        for (int i = 0; i < 4; i++) {
            int idx = tid + i * 256;          // 1024 A elems
            int o = idx >> 4, c = idx & 15;
            As[c][o] = w_qkv[(size_t)(o0 + o) * CDIM + cb + c] * s1[cb + c];
        }
#pragma unroll
        for (int i = 0; i < 4; i++) {
            int idx = tid + i * 256;
            int nl = idx & 63, c = idx >> 6;
            Bs[c][nl] = x[((size_t)b * CDIM + cb + c) * N_TOK + n0 + nl];
        }
        __syncthreads();
#pragma unroll
        for (int kk = 0; kk < 16; kk++) {
            float4 a  = *(const float4*)&As[kk][ty * 4];
            float4 bb = *(const float4*)&Bs[kk][tx * 4];
            float ar[4] = {a.x, a.y, a.z, a.w};
            float br[4] = {bb.x, bb.y, bb.z, bb.w};
#pragma unroll
            for (int i = 0; i < 4; i++)
#pragma unroll
                for (int j = 0; j < 4; j++) acc[i][j] += ar[i] * br[j];
        }
        __syncthreads();
    }
#pragma unroll
    for (int i = 0; i < 4; i++) {
        int o = o0 + ty * 4 + i;
        float bias = g_biasqkv[b * QKV_M + o];
        int kind = o >> 7;                 // 0=q,1=k,2=v
        int oc = o & 127;
        int h = oc >> 5, d = oc & 31;
#pragma unroll
        for (int j = 0; j < 4; j++) {
            int n = n0 + tx * 4 + j;
            float v = acc[i][j] + bias;
            size_t addr = ((size_t)(b * NHEADS + h) * N_TOK + n) * DHEAD + d;
            if (kind == 0)      g_q[addr] = v * QSCALE;
            else if (kind == 1) g_k[addr] = v;
            else                g_v[addr] = v;
        }
    }
}

// ---------------- 4) fp32 flash attention -------------------------------------
// Block: one (bh, 64-query tile). 256 threads. Stream 64-key tiles.
__global__ void flash_kernel() {
    __shared__ float Qst[32][68];   // [d][q]   (transposed)
    __shared__ float Kst[32][68];   // [d][k]   (transposed)
    __shared__ float Vs[64][34];    // [k][d]
    __shared__ float Ps[64][68];    // probs / staging

    const int bh = blockIdx.y;            // 0..7
    const int q0 = blockIdx.x * 64;
    const int tid = threadIdx.x;
    const int tx = tid & 15, ty = tid >> 4;

    const float* Qg = g_q + (size_t)bh * N_TOK * DHEAD;
    const float* Kg = g_k + (size_t)bh * N_TOK * DHEAD;
    const float* Vg = g_v + (size_t)bh * N_TOK * DHEAD;

    // load Q tile (transposed into Qst[d][nl])
#pragma unroll
    for (int i = 0; i < 8; i++) {
        int idx = tid + i * 256;           // 2048
        int d = idx & 31, nl = idx >> 5;
        Qst[d][nl] = Qg[(size_t)(q0 + nl) * DHEAD + d];
    }

    float m[4], l[4], o[4][2];
#pragma unroll
    for (int i = 0; i < 4; i++) { m[i] = -3.4e38f; l[i] = 0.f; o[i][0] = 0.f; o[i][1] = 0.f; }

    for (int kt = 0; kt < 64; kt++) {
        const int k0 = kt * 64;
#pragma unroll
        for (int i = 0; i < 8; i++) {
            int idx = tid + i * 256;
            int d = idx & 31, nl = idx >> 5;
            float kv = Kg[(size_t)(k0 + nl) * DHEAD + d];
            float vv = Vg[(size_t)(k0 + nl) * DHEAD + d];
            Kst[d][nl] = kv;
            Vs[nl][d]  = vv;
        }
        __syncthreads();

        float s[4][4] = {};
#pragma unroll
        for (int kk = 0; kk < 32; kk++) {
            float4 qa = *(const float4*)&Qst[kk][ty * 4];
            float4 kb = *(const float4*)&Kst[kk][tx * 4];
            float qr[4] = {qa.x, qa.y, qa.z, qa.w};
            float kr[4] = {kb.x, kb.y, kb.z, kb.w};
#pragma unroll
            for (int i = 0; i < 4; i++)
#pragma unroll
                for (int j = 0; j < 4; j++) s[i][j] += qr[i] * kr[j];
        }

        // online softmax (rows owned by ty; reduce across 16 tx lanes)
#pragma unroll
        for (int i = 0; i < 4; i++) {
            float mx = fmaxf(fmaxf(s[i][0], s[i][1]), fmaxf(s[i][2], s[i][3]));
#pragma unroll
            for (int off = 8; off; off >>= 1)
                mx = fmaxf(mx, __shfl_xor_sync(0xffffffffu, mx, off, 16));
            float mn = fmaxf(m[i], mx);
            float corr = __expf(m[i] - mn);
            float rs = 0.f;
#pragma unroll
            for (int j = 0; j < 4; j++) { s[i][j] = __expf(s[i][j] - mn); rs += s[i][j]; }
#pragma unroll
            for (int off = 8; off; off >>= 1)
                rs += __shfl_xor_sync(0xffffffffu, rs, off, 16);
            l[i] = l[i] * corr + rs;
            m[i] = mn;
            o[i][0] *= corr; o[i][1] *= corr;
            *(float4*)&Ps[ty * 4 + i][tx * 4] = make_float4(s[i][0], s[i][1], s[i][2], s[i][3]);
        }
        __syncthreads();

        // O += P @ V   (cols tx*2, tx*2+1)
#pragma unroll
        for (int j0 = 0; j0 < 64; j0 += 4) {
            float4 p[4];
#pragma unroll
            for (int i = 0; i < 4; i++) p[i] = *(const float4*)&Ps[ty * 4 + i][j0];
            float2 v[4];
#pragma unroll
            for (int jj = 0; jj < 4; jj++) v[jj] = *(const float2*)&Vs[j0 + jj][tx * 2];
#pragma unroll
            for (int i = 0; i < 4; i++) {
                o[i][0] += p[i].x * v[0].x; o[i][1] += p[i].x * v[0].y;
                o[i][0] += p[i].y * v[1].x; o[i][1] += p[i].y * v[1].y;
                o[i][0] += p[i].z * v[2].x; o[i][1] += p[i].z * v[2].y;
                o[i][0] += p[i].w * v[3].x; o[i][1] += p[i].w * v[3].y;
            }
        }
        __syncthreads();
    }

    // normalize, stage in shared (stride 33), coalesced write to [b][h*32+d][n]
    float* praw = &Ps[0][0];
#pragma unroll
    for (int i = 0; i < 4; i++) {
        float inv = 1.f / l[i];
        praw[(ty * 4 + i) * 33 + tx * 2 + 0] = o[i][0] * inv;
        praw[(ty * 4 + i) * 33 + tx * 2 + 1] = o[i][1] * inv;
    }
    __syncthreads();
    const int b = bh >> 2, h = bh & 3;
#pragma unroll
    for (int k = 0; k < 8; k++) {
        int e = tid + k * 256;             // 2048
        int d = e >> 6, nl = e & 63;
        g_ao[((size_t)b * HID + h * 32 + d) * N_TOK + q0 + nl] = praw[nl * 33 + d];
    }
}

// ---------------- 5) output projection GEMM + bias ----------------------------
__global__ void out_gemm(const float* __restrict__ w_out,
                         const float* __restrict__ b_out,
                         float* __restrict__ out) {
    __shared__ float As[16][68];
    __shared__ float Bs[16][68];
    const int b  = blockIdx.z;
    const int o0 = blockIdx.y * 64;
    const int n0 = blockIdx.x * 64;
    const int tid = threadIdx.x;
    const int tx = tid & 15, ty = tid >> 4;

    float acc[4][4] = {};
    for (int cb = 0; cb < HID; cb += 16) {
#pragma unroll
        for (int i = 0; i < 4; i++) {
            int idx = tid + i * 256;
            int o = idx >> 4, c = idx & 15;
            As[c][o] = w_out[(size_t)(o0 + o) * HID + cb + c];
        }
#pragma unroll
        for (int i = 0; i < 4; i++) {
            int idx = tid + i * 256;
            int nl = idx & 63, c = idx >> 6;
            Bs[c][nl] = g_ao[((size_t)b * HID + cb + c) * N_TOK + n0 + nl];
        }
        __syncthreads();
#pragma unroll
        for (int kk = 0; kk < 16; kk++) {
            float4 a  = *(const float4*)&As[kk][ty * 4];
            float4 bb = *(const float4*)&Bs[kk][tx * 4];
            float ar[4] = {a.x, a.y, a.z, a.w};
            float br[4] = {bb.x, bb.y, bb.z, bb.w};
#pragma unroll
            for (int i = 0; i < 4; i++)
#pragma unroll
                for (int j = 0; j < 4; j++) acc[i][j] += ar[i] * br[j];
        }
        __syncthreads();
    }
#pragma unroll
    for (int i = 0; i < 4; i++) {
        int oo = o0 + ty * 4 + i;
        float bias = b_out[oo];
#pragma unroll
        for (int j = 0; j < 4; j++) {
            int n = n0 + tx * 4 + j;
            out[((size_t)b * CDIM + oo) * N_TOK + n] = acc[i][j] + bias;
        }
    }
}

// ---------------- launch -------------------------------------------------------
extern "C" void kernel_launch(void* const* d_in, const int* in_sizes, int n_in,
                              void* d_out, int out_size) {
    const float* x      = (const float*)d_in[0];
    const float* te     = (const float*)d_in[1];
    const float* w_mlp  = (const float*)d_in[2];
    const float* b_mlp  = (const float*)d_in[3];
    const float* w_qkv  = (const float*)d_in[4];
    const float* w_out  = (const float*)d_in[5];
    const float* b_out  = (const float*)d_in[6];
    float* out = (float*)d_out;

    film_kernel<<<128, 256>>>(te, w_mlp, b_mlp);     // 1024 warps
    biasqkv_kernel<<<96, 256>>>(w_qkv);              // 768 warps
    {
        dim3 g(64, 6, 2);                            // n-tiles, o-tiles, batch
        qkv_gemm<<<g, 256>>>(x, w_qkv);
    }
    {
        dim3 g(64, 8);                               // q-tiles, bh
        flash_kernel<<<g, 256>>>();
    }
    {
        dim3 g(64, 4, 2);
        out_gemm<<<g, 256>>>(w_out, b_out, out);
    }
}

// round 3
// speedup vs baseline: 2.3408x; 2.3408x over previous
#include <cuda_runtime.h>
#include <math.h>
#include <stdint.h>

#define N_TOK   4096
#define CDIM    256
#define HID     128
#define NHEADS  4
#define DHEAD   32
#define QKV_M   384
#define TDIM    512
#define QSCALE  0.17677669529663687f   // 32^-0.5
#define FULLMASK 0xffffffffu

// ---------------- scratch (static device globals; no allocation) -------------
__device__ float g_s1[2 * CDIM];        // scale + 1
__device__ float g_shift[2 * CDIM];
__device__ float g_biasqkv[2 * QKV_M];  // sum_c w_qkv[o,c] * shift[b,c]
__device__ float g_q[8 * N_TOK * DHEAD];   // [bh][n][d], pre-scaled by QSCALE
__device__ float g_k[8 * N_TOK * DHEAD];   // [bh][n][d]
__device__ float g_v[8 * DHEAD * N_TOK];   // [bh][d][n]  (TRANSPOSED for PV mma)
__device__ float g_ao[2 * HID * N_TOK];    // attention out [b][h*32+d][n]

// ======================= helpers =============================================
__device__ __forceinline__ float f2tf(float f) {
    uint32_t u;
    asm("cvt.rna.tf32.f32 %0, %1;" : "=r"(u) : "f"(f));
    return __uint_as_float(u);
}
// D += A(tf32 m16k8) * B(tf32 k8n8)  -- register-fragment tensor-core mma
__device__ __forceinline__ void mma8(float* d, float a0, float a1, float a2, float a3,
                                     float b0, float b1) {
    asm volatile(
        "mma.sync.aligned.m16n8k8.row.col.f32.tf32.tf32.f32 "
        "{%0,%1,%2,%3}, {%4,%5,%6,%7}, {%8,%9}, {%0,%1,%2,%3};"
        : "+f"(d[0]), "+f"(d[1]), "+f"(d[2]), "+f"(d[3])
        : "r"(__float_as_uint(a0)), "r"(__float_as_uint(a1)),
          "r"(__float_as_uint(a2)), "r"(__float_as_uint(a3)),
          "r"(__float_as_uint(b0)), "r"(__float_as_uint(b1)));
}

// ---------------- 1) FiLM MLP: t = silu(te) @ w_mlp^T + b_mlp ---------------
__global__ void film_kernel(const float* __restrict__ te,
                            const float* __restrict__ w_mlp,
                            const float* __restrict__ b_mlp) {
    int gw   = (blockIdx.x * blockDim.x + threadIdx.x) >> 5;
    int lane = threadIdx.x & 31;
    if (gw >= 2 * 2 * CDIM) return;
    int b = gw / (2 * CDIM);
    int j = gw % (2 * CDIM);
    const float* e = te + b * TDIM;
    const float* wr = w_mlp + (size_t)j * TDIM;
    float s = 0.f;
    for (int i = lane; i < TDIM; i += 32) {
        float x  = e[i];
        float si = x / (1.f + __expf(-x));
        s += si * wr[i];
    }
#pragma unroll
    for (int o = 16; o; o >>= 1) s += __shfl_xor_sync(FULLMASK, s, o);
    if (lane == 0) {
        float t = s + b_mlp[j];
        if (j < CDIM) g_s1[b * CDIM + j] = t + 1.f;
        else          g_shift[b * CDIM + (j - CDIM)] = t;
    }
}

// ---------------- 2) bias_qkv[b][o] = sum_c w_qkv[o,c] * shift[b,c] ----------
__global__ void biasqkv_kernel(const float* __restrict__ w_qkv) {
    int gw   = (blockIdx.x * blockDim.x + threadIdx.x) >> 5;
    int lane = threadIdx.x & 31;
    if (gw >= 2 * QKV_M) return;
    int b = gw / QKV_M;
    int o = gw % QKV_M;
    const float* wr = w_qkv + (size_t)o * CDIM;
    const float* sh = g_shift + b * CDIM;
    float s = 0.f;
    for (int c = lane; c < CDIM; c += 32) s += wr[c] * sh[c];
#pragma unroll
    for (int off = 16; off; off >>= 1) s += __shfl_xor_sync(FULLMASK, s, off);
    if (lane == 0) g_biasqkv[b * QKV_M + o] = s;
}

// ---------------- 3) QKV GEMM (FiLM folded in) --------------------------------
__global__ void qkv_gemm(const float* __restrict__ x,
                         const float* __restrict__ w_qkv) {
    __shared__ float As[16][68];
    __shared__ float Bs[16][68];
    const int b  = blockIdx.z;
    const int o0 = blockIdx.y * 64;
    const int n0 = blockIdx.x * 64;
    const int tid = threadIdx.x;
    const int tx = tid & 15, ty = tid >> 4;

    float acc[4][4] = {};
    const float* s1 = g_s1 + b * CDIM;
    for (int cb = 0; cb < CDIM; cb += 16) {
#pragma unroll
        for (int i = 0; i < 4; i++) {
            int idx = tid + i * 256;
            int o = idx >> 4, c = idx & 15;
            As[c][o] = w_qkv[(size_t)(o0 + o) * CDIM + cb + c] * s1[cb + c];
        }
#pragma unroll
        for (int i = 0; i < 4; i++) {
            int idx = tid + i * 256;
            int nl = idx & 63, c = idx >> 6;
            Bs[c][nl] = x[((size_t)b * CDIM + cb + c) * N_TOK + n0 + nl];
        }
        __syncthreads();
#pragma unroll
        for (int kk = 0; kk < 16; kk++) {
            float4 a  = *(const float4*)&As[kk][ty * 4];
            float4 bb = *(const float4*)&Bs[kk][tx * 4];
            float ar[4] = {a.x, a.y, a.z, a.w};
            float br[4] = {bb.x, bb.y, bb.z, bb.w};
#pragma unroll
            for (int i = 0; i < 4; i++)
#pragma unroll
                for (int j = 0; j < 4; j++) acc[i][j] += ar[i] * br[j];
        }
        __syncthreads();
    }
#pragma unroll
    for (int i = 0; i < 4; i++) {
        int o = o0 + ty * 4 + i;
        float bias = g_biasqkv[b * QKV_M + o];
        int kind = o >> 7;                 // 0=q,1=k,2=v
        int oc = o & 127;
        int h = oc >> 5, d = oc & 31;
#pragma unroll
        for (int j = 0; j < 4; j++) {
            int n = n0 + tx * 4 + j;
            float v = acc[i][j] + bias;
            if (kind == 0)
                g_q[((size_t)(b * NHEADS + h) * N_TOK + n) * DHEAD + d] = v * QSCALE;
            else if (kind == 1)
                g_k[((size_t)(b * NHEADS + h) * N_TOK + n) * DHEAD + d] = v;
            else  // v transposed: [bh][d][n]
                g_v[((size_t)(b * NHEADS + h) * DHEAD + d) * N_TOK + n] = v;
        }
    }
}

// ---------------- 4) tf32 mma.sync flash attention -----------------------------
// 8 warps / block; warp w owns q rows [q0+16w, q0+16w+16). 64-key tiles.
// K/V staged in SMEM pre-swizzled into exact B-fragment order (tf32-rounded).
__global__ __launch_bounds__(256) void flash_mma() {
    __shared__ float sraw[32 * 129];        // 16.5KB; also frag area (4096 floats)
    float* Kf = sraw;                       // [j:8][kk:4][lane:32][r:2]
    float* Vf = sraw + 2048;                // [n:4][ks:8][lane:32][r:2]

    const int tid  = threadIdx.x;
    const int lane = tid & 31, wid = tid >> 5;
    const int g    = lane >> 2, tig = lane & 3;
    const int bh   = blockIdx.y;
    const int q0   = blockIdx.x * 128;

    const float* Qg = g_q + (size_t)bh * N_TOK * DHEAD;
    const float* Kg = g_k + (size_t)bh * N_TOK * DHEAD;
    const float* Vg = g_v + (size_t)bh * DHEAD * N_TOK;

    // Q A-fragments (held for whole kernel)
    float qa[4][4];
    const int qrow = q0 + wid * 16 + g;
#pragma unroll
    for (int kk = 0; kk < 4; kk++) {
        qa[kk][0] = f2tf(Qg[(size_t)qrow       * 32 + kk * 8 + tig]);
        qa[kk][1] = f2tf(Qg[(size_t)(qrow + 8) * 32 + kk * 8 + tig]);
        qa[kk][2] = f2tf(Qg[(size_t)qrow       * 32 + kk * 8 + tig + 4]);
        qa[kk][3] = f2tf(Qg[(size_t)(qrow + 8) * 32 + kk * 8 + tig + 4]);
    }

    float o[4][4] = {};
    float m0 = -1e30f, m1 = -1e30f, l0 = 0.f, l1 = 0.f;

    const int srcA = (lane & ~3) | (tig >> 1);
    const int srcB = srcA + 2;
    const bool hi  = tig & 1;

    for (int kt = 0; kt < 64; kt++) {
        const int k0 = kt * 64;
        // ---- stage K into fragment layout ----
#pragma unroll
        for (int i = 0; i < 8; i++) {
            int idx = tid + i * 256;
            int key = idx >> 5, d = idx & 31;
            float v = f2tf(Kg[(size_t)(k0 + key) * 32 + d]);
            int j = key >> 3, gg = key & 7, kk = d >> 3, dd = d & 7;
            Kf[((j * 4 + kk) * 32 + gg * 4 + (dd & 3)) * 2 + (dd >> 2)] = v;
        }
        // ---- stage V into fragment layout ----
#pragma unroll
        for (int i = 0; i < 8; i++) {
            int idx = tid + i * 256;
            int d = idx >> 6, key = idx & 63;
            float v = f2tf(Vg[(size_t)d * N_TOK + k0 + key]);
            int ks = key >> 3, kw = key & 7, n = d >> 3, gg = d & 7;
            Vf[((n * 8 + ks) * 32 + gg * 4 + (kw & 3)) * 2 + (kw >> 2)] = v;
        }
        __syncthreads();

        // ---- S = Q @ K^T : 32 mmas ----
        float s[8][4];
#pragma unroll
        for (int j = 0; j < 8; j++) {
            s[j][0] = 0.f; s[j][1] = 0.f; s[j][2] = 0.f; s[j][3] = 0.f;
#pragma unroll
            for (int kk = 0; kk < 4; kk++) {
                float2 bf = *(const float2*)&Kf[((j * 4 + kk) * 32 + lane) * 2];
                mma8(s[j], qa[kk][0], qa[kk][1], qa[kk][2], qa[kk][3], bf.x, bf.y);
            }
        }

        // ---- online softmax (rows g, g+8) ----
        float mx0 = -1e30f, mx1 = -1e30f;
#pragma unroll
        for (int j = 0; j < 8; j++) {
            mx0 = fmaxf(mx0, fmaxf(s[j][0], s[j][1]));
            mx1 = fmaxf(mx1, fmaxf(s[j][2], s[j][3]));
        }
        mx0 = fmaxf(mx0, __shfl_xor_sync(FULLMASK, mx0, 1));
        mx0 = fmaxf(mx0, __shfl_xor_sync(FULLMASK, mx0, 2));
        mx1 = fmaxf(mx1, __shfl_xor_sync(FULLMASK, mx1, 1));
        mx1 = fmaxf(mx1, __shfl_xor_sync(FULLMASK, mx1, 2));
        float mn0 = fmaxf(m0, mx0), mn1 = fmaxf(m1, mx1);
        float corr0 = __expf(m0 - mn0), corr1 = __expf(m1 - mn1);
        float rs0 = 0.f, rs1 = 0.f;
#pragma unroll
        for (int j = 0; j < 8; j++) {
            s[j][0] = f2tf(__expf(s[j][0] - mn0));
            s[j][1] = f2tf(__expf(s[j][1] - mn0));
            s[j][2] = f2tf(__expf(s[j][2] - mn1));
            s[j][3] = f2tf(__expf(s[j][3] - mn1));
            rs0 += s[j][0] + s[j][1];
            rs1 += s[j][2] + s[j][3];
        }
        rs0 += __shfl_xor_sync(FULLMASK, rs0, 1);
        rs0 += __shfl_xor_sync(FULLMASK, rs0, 2);
        rs1 += __shfl_xor_sync(FULLMASK, rs1, 1);
        rs1 += __shfl_xor_sync(FULLMASK, rs1, 2);
        l0 = l0 * corr0 + rs0;  m0 = mn0;
        l1 = l1 * corr1 + rs1;  m1 = mn1;

#pragma unroll
        for (int n = 0; n < 4; n++) {
            o[n][0] *= corr0; o[n][1] *= corr0;
            o[n][2] *= corr1; o[n][3] *= corr1;
        }

        // ---- O += P @ V : re-lay P into A-fragments via quad shuffles ----
#pragma unroll
        for (int ks = 0; ks < 8; ks++) {
            float v0 = __shfl_sync(FULLMASK, s[ks][0], srcA);
            float v1 = __shfl_sync(FULLMASK, s[ks][1], srcA);
            float v2 = __shfl_sync(FULLMASK, s[ks][2], srcA);
            float v3 = __shfl_sync(FULLMASK, s[ks][3], srcA);
            float w0 = __shfl_sync(FULLMASK, s[ks][0], srcB);
            float w1 = __shfl_sync(FULLMASK, s[ks][1], srcB);
            float w2 = __shfl_sync(FULLMASK, s[ks][2], srcB);
            float w3 = __shfl_sync(FULLMASK, s[ks][3], srcB);
            float a0 = hi ? v1 : v0;
            float a1 = hi ? v3 : v2;
            float a2 = hi ? w1 : w0;
            float a3 = hi ? w3 : w2;
#pragma unroll
            for (int n = 0; n < 4; n++) {
                float2 bf = *(const float2*)&Vf[((n * 8 + ks) * 32 + lane) * 2];
                mma8(o[n], a0, a1, a2, a3, bf.x, bf.y);
            }
        }
        __syncthreads();
    }

    // ---- epilogue: normalize, stage via smem, coalesced write ----
    float inv0 = 1.f / l0, inv1 = 1.f / l1;
#pragma unroll
    for (int n = 0; n < 4; n++) {
#pragma unroll
        for (int c = 0; c < 2; c++) {
            int d = n * 8 + 2 * tig + c;
            sraw[d * 129 + wid * 16 + g]     = o[n][c]     * inv0;
            sraw[d * 129 + wid * 16 + g + 8] = o[n][2 + c] * inv1;
        }
    }
    __syncthreads();
    const int b = bh >> 2, h = bh & 3;
#pragma unroll
    for (int i = 0; i < 16; i++) {
        int idx = tid + i * 256;          // 4096 elems
        int d = idx >> 7, tok = idx & 127;
        g_ao[((size_t)b * HID + h * 32 + d) * N_TOK + q0 + tok] = sraw[d * 129 + tok];
    }
}

// ---------------- 5) output projection GEMM + bias ----------------------------
__global__ void out_gemm(const float* __restrict__ w_out,
                         const float* __restrict__ b_out,
                         float* __restrict__ out) {
    __shared__ float As[16][68];
    __shared__ float Bs[16][68];
    const int b  = blockIdx.z;
    const int o0 = blockIdx.y * 64;
    const int n0 = blockIdx.x * 64;
    const int tid = threadIdx.x;
    const int tx = tid & 15, ty = tid >> 4;

    float acc[4][4] = {};
    for (int cb = 0; cb < HID; cb += 16) {
#pragma unroll
        for (int i = 0; i < 4; i++) {
            int idx = tid + i * 256;
            int o = idx >> 4, c = idx & 15;
            As[c][o] = w_out[(size_t)(o0 + o) * HID + cb + c];
        }
#pragma unroll
        for (int i = 0; i < 4; i++) {
            int idx = tid + i * 256;
            int nl = idx & 63, c = idx >> 6;
            Bs[c][nl] = g_ao[((size_t)b * HID + cb + c) * N_TOK + n0 + nl];
        }
        __syncthreads();
#pragma unroll
        for (int kk = 0; kk < 16; kk++) {
            float4 a  = *(const float4*)&As[kk][ty * 4];
            float4 bb = *(const float4*)&Bs[kk][tx * 4];
            float ar[4] = {a.x, a.y, a.z, a.w};
            float br[4] = {bb.x, bb.y, bb.z, bb.w};
#pragma unroll
            for (int i = 0; i < 4; i++)
#pragma unroll
                for (int j = 0; j < 4; j++) acc[i][j] += ar[i] * br[j];
        }
        __syncthreads();
    }
#pragma unroll
    for (int i = 0; i < 4; i++) {
        int oo = o0 + ty * 4 + i;
        float bias = b_out[oo];
#pragma unroll
        for (int j = 0; j < 4; j++) {
            int n = n0 + tx * 4 + j;
            out[((size_t)b * CDIM + oo) * N_TOK + n] = acc[i][j] + bias;
        }
    }
}

// ---------------- launch -------------------------------------------------------
extern "C" void kernel_launch(void* const* d_in, const int* in_sizes, int n_in,
                              void* d_out, int out_size) {
    const float* x      = (const float*)d_in[0];
    const float* te     = (const float*)d_in[1];
    const float* w_mlp  = (const float*)d_in[2];
    const float* b_mlp  = (const float*)d_in[3];
    const float* w_qkv  = (const float*)d_in[4];
    const float* w_out  = (const float*)d_in[5];
    const float* b_out  = (const float*)d_in[6];
    float* out = (float*)d_out;

    film_kernel<<<128, 256>>>(te, w_mlp, b_mlp);
    biasqkv_kernel<<<96, 256>>>(w_qkv);
    {
        dim3 g(64, 6, 2);
        qkv_gemm<<<g, 256>>>(x, w_qkv);
    }
    {
        dim3 g(32, 8);                     // 128-query tiles x bh
        flash_mma<<<g, 256>>>();
    }
    {
        dim3 g(64, 4, 2);
        out_gemm<<<g, 256>>>(w_out, b_out, out);
    }
}

// round 4
// speedup vs baseline: 3.4677x; 1.4814x over previous
#include <cuda_runtime.h>
#include <cuda_fp16.h>
#include <math.h>
#include <stdint.h>

#define N_TOK   4096
#define CDIM    256
#define HID     128
#define NHEADS  4
#define DHEAD   32
#define QKV_M   384
#define TDIM    512
#define QSCALE  0.17677669529663687f   // 32^-0.5
#define FULLMASK 0xffffffffu

// ---------------- scratch (static device globals; no allocation) -------------
__device__ float  g_s1[2 * CDIM];
__device__ float  g_shift[2 * CDIM];
__device__ float  g_biasqkv[2 * QKV_M];
__device__ __half g_q[8 * N_TOK * DHEAD];   // [bh][n][d], pre-scaled by QSCALE
__device__ __half g_k[8 * N_TOK * DHEAD];   // [bh][n][d]
__device__ __half g_v[8 * DHEAD * N_TOK];   // [bh][d][n]  (transposed for PV)
__device__ float  g_ao[2 * HID * N_TOK];    // attention out [b][h*32+d][n]

// ======================= helpers =============================================
// D += A(f16 m16k16) * B(f16 k16n8), f32 accumulate
__device__ __forceinline__ void mma16(float* d, uint32_t a0, uint32_t a1,
                                      uint32_t a2, uint32_t a3,
                                      uint32_t b0, uint32_t b1) {
    asm volatile(
        "mma.sync.aligned.m16n8k16.row.col.f32.f16.f16.f32 "
        "{%0,%1,%2,%3}, {%4,%5,%6,%7}, {%8,%9}, {%0,%1,%2,%3};"
        : "+f"(d[0]), "+f"(d[1]), "+f"(d[2]), "+f"(d[3])
        : "r"(a0), "r"(a1), "r"(a2), "r"(a3), "r"(b0), "r"(b1));
}
__device__ __forceinline__ uint32_t packh2(float lo, float hi) {
    uint32_t u;
    asm("cvt.rn.f16x2.f32 %0, %1, %2;" : "=r"(u) : "f"(hi), "f"(lo));
    return u;
}

// ---------------- 1) FiLM MLP ------------------------------------------------
__global__ void film_kernel(const float* __restrict__ te,
                            const float* __restrict__ w_mlp,
                            const float* __restrict__ b_mlp) {
    int gw   = (blockIdx.x * blockDim.x + threadIdx.x) >> 5;
    int lane = threadIdx.x & 31;
    if (gw >= 2 * 2 * CDIM) return;
    int b = gw / (2 * CDIM);
    int j = gw % (2 * CDIM);
    const float* e = te + b * TDIM;
    const float* wr = w_mlp + (size_t)j * TDIM;
    float s = 0.f;
    for (int i = lane; i < TDIM; i += 32) {
        float x  = e[i];
        float si = x / (1.f + __expf(-x));
        s += si * wr[i];
    }
#pragma unroll
    for (int o = 16; o; o >>= 1) s += __shfl_xor_sync(FULLMASK, s, o);
    if (lane == 0) {
        float t = s + b_mlp[j];
        if (j < CDIM) g_s1[b * CDIM + j] = t + 1.f;
        else          g_shift[b * CDIM + (j - CDIM)] = t;
    }
}

// ---------------- 2) bias_qkv ------------------------------------------------
__global__ void biasqkv_kernel(const float* __restrict__ w_qkv) {
    int gw   = (blockIdx.x * blockDim.x + threadIdx.x) >> 5;
    int lane = threadIdx.x & 31;
    if (gw >= 2 * QKV_M) return;
    int b = gw / QKV_M;
    int o = gw % QKV_M;
    const float* wr = w_qkv + (size_t)o * CDIM;
    const float* sh = g_shift + b * CDIM;
    float s = 0.f;
    for (int c = lane; c < CDIM; c += 32) s += wr[c] * sh[c];
#pragma unroll
    for (int off = 16; off; off >>= 1) s += __shfl_xor_sync(FULLMASK, s, off);
    if (lane == 0) g_biasqkv[b * QKV_M + o] = s;
}

// ---------------- 3) QKV GEMM (FiLM folded, f16 outputs) ----------------------
__global__ void qkv_gemm(const float* __restrict__ x,
                         const float* __restrict__ w_qkv) {
    __shared__ float As[16][68];
    __shared__ float Bs[16][68];
    const int b  = blockIdx.z;
    const int o0 = blockIdx.y * 64;
    const int n0 = blockIdx.x * 64;
    const int tid = threadIdx.x;
    const int tx = tid & 15, ty = tid >> 4;

    float acc[4][4] = {};
    const float* s1 = g_s1 + b * CDIM;
    for (int cb = 0; cb < CDIM; cb += 16) {
#pragma unroll
        for (int i = 0; i < 4; i++) {
            int idx = tid + i * 256;
            int o = idx >> 4, c = idx & 15;
            As[c][o] = w_qkv[(size_t)(o0 + o) * CDIM + cb + c] * s1[cb + c];
        }
#pragma unroll
        for (int i = 0; i < 4; i++) {
            int idx = tid + i * 256;
            int nl = idx & 63, c = idx >> 6;
            Bs[c][nl] = x[((size_t)b * CDIM + cb + c) * N_TOK + n0 + nl];
        }
        __syncthreads();
#pragma unroll
        for (int kk = 0; kk < 16; kk++) {
            float4 a  = *(const float4*)&As[kk][ty * 4];
            float4 bb = *(const float4*)&Bs[kk][tx * 4];
            float ar[4] = {a.x, a.y, a.z, a.w};
            float br[4] = {bb.x, bb.y, bb.z, bb.w};
#pragma unroll
            for (int i = 0; i < 4; i++)
#pragma unroll
                for (int j = 0; j < 4; j++) acc[i][j] += ar[i] * br[j];
        }
        __syncthreads();
    }
#pragma unroll
    for (int i = 0; i < 4; i++) {
        int o = o0 + ty * 4 + i;
        float bias = g_biasqkv[b * QKV_M + o];
        int kind = o >> 7;                 // 0=q,1=k,2=v
        int oc = o & 127;
        int h = oc >> 5, d = oc & 31;
#pragma unroll
        for (int j = 0; j < 4; j++) {
            int n = n0 + tx * 4 + j;
            float v = acc[i][j] + bias;
            if (kind == 0)
                g_q[((size_t)(b * NHEADS + h) * N_TOK + n) * DHEAD + d] =
                    __float2half(v * QSCALE);
            else if (kind == 1)
                g_k[((size_t)(b * NHEADS + h) * N_TOK + n) * DHEAD + d] = __float2half(v);
            else
                g_v[((size_t)(b * NHEADS + h) * DHEAD + d) * N_TOK + n] = __float2half(v);
        }
    }
}

// ---------------- 4) f16 mma.sync flash attention ------------------------------
// 8 warps/block; warp owns 16 q rows. 64-key tiles, double-buffered fragments.
// Fragment smem layout (per buffer, uint2 per lane):
//   K blocks (j*2+kk), j=key/8 kk=d-chunk/16 : kbuf[(j*2+kk)*32 + lane]
//   V blocks (n*4+kk), n=d/8  kk=key-chunk/16: vbuf[(n*4+kk)*32 + lane]
__global__ __launch_bounds__(256) void flash_mma() {
    __shared__ float sraw[32 * 129];    // 16.5KB: frag buffers (16KB) + epilogue

    const int tid  = threadIdx.x;
    const int lane = tid & 31, wid = tid >> 5;
    const int g    = lane >> 2, tig = lane & 3;
    const int bh   = blockIdx.y;
    const int q0   = blockIdx.x * 128;

    const __half* Qg = g_q + (size_t)bh * N_TOK * DHEAD;
    const __half* Kg = g_k + (size_t)bh * N_TOK * DHEAD;
    const __half* Vg = g_v + (size_t)bh * DHEAD * N_TOK;

    // Q A-fragments, held in registers: qa[kk][0..3], kk = d-chunk of 16
    uint32_t qa[2][4];
    const int qrow = q0 + wid * 16 + g;
#pragma unroll
    for (int kk = 0; kk < 2; kk++) {
        const __half* base = Qg + (size_t)qrow * DHEAD + kk * 16 + 2 * tig;
        qa[kk][0] = *(const uint32_t*)(base);
        qa[kk][1] = *(const uint32_t*)(base + 8 * DHEAD);
        qa[kk][2] = *(const uint32_t*)(base + 8);
        qa[kk][3] = *(const uint32_t*)(base + 8 * DHEAD + 8);
    }

    float o[4][4] = {};
    float m0 = -1e30f, m1 = -1e30f, l0 = 0.f, l1 = 0.f;

    for (int kt = 0; kt < 64; kt++) {
        const int k0 = kt * 64;
        uint2* fb   = ((uint2*)sraw) + (kt & 1) * 1024;
        uint2* kbuf = fb;
        uint2* vbuf = fb + 512;

        // ---- stage: threads 0-127 -> K, 128-255 -> V (LDG.128 + STS.128) ----
        if (tid < 128) {
            int key = tid >> 1, kk = tid & 1;
            const uint4* src = (const uint4*)(Kg + (size_t)(k0 + key) * DHEAD + kk * 16);
            uint4 lo = src[0], hi = src[1];
            uint4* dst = (uint4*)(kbuf + (((key >> 3) * 2 + kk) * 32 + (key & 7) * 4));
            dst[0] = make_uint4(lo.x, hi.x, lo.y, hi.y);
            dst[1] = make_uint4(lo.z, hi.z, lo.w, hi.w);
        } else {
            int u = tid - 128;
            int d = u >> 2, kk = u & 3;
            const uint4* src = (const uint4*)(Vg + (size_t)d * N_TOK + k0 + kk * 16);
            uint4 lo = src[0], hi = src[1];
            uint4* dst = (uint4*)(vbuf + (((d >> 3) * 4 + kk) * 32 + (d & 7) * 4));
            dst[0] = make_uint4(lo.x, hi.x, lo.y, hi.y);
            dst[1] = make_uint4(lo.z, hi.z, lo.w, hi.w);
        }
        __syncthreads();

        // ---- S = Q @ K^T : 16 mmas ----
        float s[8][4];
#pragma unroll
        for (int j = 0; j < 8; j++) {
            s[j][0] = 0.f; s[j][1] = 0.f; s[j][2] = 0.f; s[j][3] = 0.f;
#pragma unroll
            for (int kk = 0; kk < 2; kk++) {
                uint2 b = kbuf[(j * 2 + kk) * 32 + lane];
                mma16(s[j], qa[kk][0], qa[kk][1], qa[kk][2], qa[kk][3], b.x, b.y);
            }
        }

        // ---- online softmax (rows g, g+8; reduce over quad) ----
        float mx0 = -1e30f, mx1 = -1e30f;
#pragma unroll
        for (int j = 0; j < 8; j++) {
            mx0 = fmaxf(mx0, fmaxf(s[j][0], s[j][1]));
            mx1 = fmaxf(mx1, fmaxf(s[j][2], s[j][3]));
        }
        mx0 = fmaxf(mx0, __shfl_xor_sync(FULLMASK, mx0, 1));
        mx0 = fmaxf(mx0, __shfl_xor_sync(FULLMASK, mx0, 2));
        mx1 = fmaxf(mx1, __shfl_xor_sync(FULLMASK, mx1, 1));
        mx1 = fmaxf(mx1, __shfl_xor_sync(FULLMASK, mx1, 2));
        float mn0 = fmaxf(m0, mx0), mn1 = fmaxf(m1, mx1);
        float corr0 = __expf(m0 - mn0), corr1 = __expf(m1 - mn1);
        float rs0 = 0.f, rs1 = 0.f;
#pragma unroll
        for (int j = 0; j < 8; j++) {
            s[j][0] = __expf(s[j][0] - mn0);
            s[j][1] = __expf(s[j][1] - mn0);
            s[j][2] = __expf(s[j][2] - mn1);
            s[j][3] = __expf(s[j][3] - mn1);
            rs0 += s[j][0] + s[j][1];
            rs1 += s[j][2] + s[j][3];
        }
        rs0 += __shfl_xor_sync(FULLMASK, rs0, 1);
        rs0 += __shfl_xor_sync(FULLMASK, rs0, 2);
        rs1 += __shfl_xor_sync(FULLMASK, rs1, 1);
        rs1 += __shfl_xor_sync(FULLMASK, rs1, 2);
        l0 = l0 * corr0 + rs0;  m0 = mn0;
        l1 = l1 * corr1 + rs1;  m1 = mn1;

#pragma unroll
        for (int n = 0; n < 4; n++) {
            o[n][0] *= corr0; o[n][1] *= corr0;
            o[n][2] *= corr1; o[n][3] *= corr1;
        }

        // ---- O += P @ V : C-fragment of S IS the A-fragment of P (f16 pack) ----
#pragma unroll
        for (int kk = 0; kk < 4; kk++) {
            uint32_t a0 = packh2(s[2 * kk][0],     s[2 * kk][1]);
            uint32_t a1 = packh2(s[2 * kk][2],     s[2 * kk][3]);
            uint32_t a2 = packh2(s[2 * kk + 1][0], s[2 * kk + 1][1]);
            uint32_t a3 = packh2(s[2 * kk + 1][2], s[2 * kk + 1][3]);
#pragma unroll
            for (int n = 0; n < 4; n++) {
                uint2 b = vbuf[(n * 4 + kk) * 32 + lane];
                mma16(o[n], a0, a1, a2, a3, b.x, b.y);
            }
        }
    }

    // ---- epilogue: normalize, stage via smem, coalesced write ----
    __syncthreads();   // all warps done reading fragment buffers
    float inv0 = 1.f / l0, inv1 = 1.f / l1;
#pragma unroll
    for (int n = 0; n < 4; n++) {
#pragma unroll
        for (int c = 0; c < 2; c++) {
            int d = n * 8 + 2 * tig + c;
            sraw[d * 129 + wid * 16 + g]     = o[n][c]     * inv0;
            sraw[d * 129 + wid * 16 + g + 8] = o[n][2 + c] * inv1;
        }
    }
    __syncthreads();
    const int b = bh >> 2, h = bh & 3;
#pragma unroll
    for (int i = 0; i < 16; i++) {
        int idx = tid + i * 256;          // 4096 elems
        int d = idx >> 7, tok = idx & 127;
        g_ao[((size_t)b * HID + h * 32 + d) * N_TOK + q0 + tok] = sraw[d * 129 + tok];
    }
}

// ---------------- 5) output projection GEMM + bias ----------------------------
__global__ void out_gemm(const float* __restrict__ w_out,
                         const float* __restrict__ b_out,
                         float* __restrict__ out) {
    __shared__ float As[16][68];
    __shared__ float Bs[16][68];
    const int b  = blockIdx.z;
    const int o0 = blockIdx.y * 64;
    const int n0 = blockIdx.x * 64;
    const int tid = threadIdx.x;
    const int tx = tid & 15, ty = tid >> 4;

    float acc[4][4] = {};
    for (int cb = 0; cb < HID; cb += 16) {
#pragma unroll
        for (int i = 0; i < 4; i++) {
            int idx = tid + i * 256;
            int o = idx >> 4, c = idx & 15;
            As[c][o] = w_out[(size_t)(o0 + o) * HID + cb + c];
        }
#pragma unroll
        for (int i = 0; i < 4; i++) {
            int idx = tid + i * 256;
            int nl = idx & 63, c = idx >> 6;
            Bs[c][nl] = g_ao[((size_t)b * HID + cb + c) * N_TOK + n0 + nl];
        }
        __syncthreads();
#pragma unroll
        for (int kk = 0; kk < 16; kk++) {
            float4 a  = *(const float4*)&As[kk][ty * 4];
            float4 bb = *(const float4*)&Bs[kk][tx * 4];
            float ar[4] = {a.x, a.y, a.z, a.w};
            float br[4] = {bb.x, bb.y, bb.z, bb.w};
#pragma unroll
            for (int i = 0; i < 4; i++)
#pragma unroll
                for (int j = 0; j < 4; j++) acc[i][j] += ar[i] * br[j];
        }
        __syncthreads();
    }
#pragma unroll
    for (int i = 0; i < 4; i++) {
        int oo = o0 + ty * 4 + i;
        float bias = b_out[oo];
#pragma unroll
        for (int j = 0; j < 4; j++) {
            int n = n0 + tx * 4 + j;
            out[((size_t)b * CDIM + oo) * N_TOK + n] = acc[i][j] + bias;
        }
    }
}

// ---------------- launch -------------------------------------------------------
extern "C" void kernel_launch(void* const* d_in, const int* in_sizes, int n_in,
                              void* d_out, int out_size) {
    const float* x      = (const float*)d_in[0];
    const float* te     = (const float*)d_in[1];
    const float* w_mlp  = (const float*)d_in[2];
    const float* b_mlp  = (const float*)d_in[3];
    const float* w_qkv  = (const float*)d_in[4];
    const float* w_out  = (const float*)d_in[5];
    const float* b_out  = (const float*)d_in[6];
    float* out = (float*)d_out;

    film_kernel<<<128, 256>>>(te, w_mlp, b_mlp);
    biasqkv_kernel<<<96, 256>>>(w_qkv);
    {
        dim3 g(64, 6, 2);
        qkv_gemm<<<g, 256>>>(x, w_qkv);
    }
    {
        dim3 g(32, 8);                     // 128-query tiles x bh
        flash_mma<<<g, 256>>>();
    }
    {
        dim3 g(64, 4, 2);
        out_gemm<<<g, 256>>>(w_out, b_out, out);
    }
}

// round 5
// speedup vs baseline: 5.0602x; 1.4592x over previous
#include <cuda_runtime.h>
#include <cuda_fp16.h>
#include <math.h>
#include <stdint.h>

#define N_TOK   4096
#define CDIM    256
#define HID     128
#define NHEADS  4
#define DHEAD   32
#define QKV_M   384
#define TDIM    512
#define QSCALE  0.17677669529663687f   // 32^-0.5
#define FULLMASK 0xffffffffu

// ---------------- scratch (static device globals; no allocation) -------------
__device__ float  g_s1[2 * CDIM];
__device__ float  g_shift[2 * CDIM];
__device__ float  g_biasqkv[2 * QKV_M];
__device__ __half g_wqh[2 * QKV_M * CDIM];   // (w_qkv * s1) per batch, half
__device__ __half g_xh[2 * N_TOK * CDIM];    // x transposed [b][n][c], half
__device__ __half g_woh[CDIM * HID];         // w_out half
__device__ __half g_q[8 * N_TOK * DHEAD];    // [bh][n][d], pre-scaled
__device__ __half g_k[8 * N_TOK * DHEAD];    // [bh][n][d]
__device__ __half g_v[8 * DHEAD * N_TOK];    // [bh][d][n]
__device__ __half g_aoh[2 * N_TOK * HID];    // attn out [b][n][h*32+d], half

// ======================= helpers =============================================
__device__ __forceinline__ void mma16(float* d, uint32_t a0, uint32_t a1,
                                      uint32_t a2, uint32_t a3,
                                      uint32_t b0, uint32_t b1) {
    asm volatile(
        "mma.sync.aligned.m16n8k16.row.col.f32.f16.f16.f32 "
        "{%0,%1,%2,%3}, {%4,%5,%6,%7}, {%8,%9}, {%0,%1,%2,%3};"
        : "+f"(d[0]), "+f"(d[1]), "+f"(d[2]), "+f"(d[3])
        : "r"(a0), "r"(a1), "r"(a2), "r"(a3), "r"(b0), "r"(b1));
}
__device__ __forceinline__ uint32_t packh2(float lo, float hi) {
    uint32_t u;
    asm("cvt.rn.f16x2.f32 %0, %1, %2;" : "=r"(u) : "f"(hi), "f"(lo));
    return u;
}

// ---------------- 1) FiLM MLP ------------------------------------------------
__global__ void film_kernel(const float* __restrict__ te,
                            const float* __restrict__ w_mlp,
                            const float* __restrict__ b_mlp) {
    int gw   = (blockIdx.x * blockDim.x + threadIdx.x) >> 5;
    int lane = threadIdx.x & 31;
    if (gw >= 2 * 2 * CDIM) return;
    int b = gw / (2 * CDIM);
    int j = gw % (2 * CDIM);
    const float* e = te + b * TDIM;
    const float* wr = w_mlp + (size_t)j * TDIM;
    float s = 0.f;
    for (int i = lane; i < TDIM; i += 32) {
        float x  = e[i];
        float si = x / (1.f + __expf(-x));
        s += si * wr[i];
    }
#pragma unroll
    for (int o = 16; o; o >>= 1) s += __shfl_xor_sync(FULLMASK, s, o);
    if (lane == 0) {
        float t = s + b_mlp[j];
        if (j < CDIM) g_s1[b * CDIM + j] = t + 1.f;
        else          g_shift[b * CDIM + (j - CDIM)] = t;
    }
}

// ---------------- 2) prep: wqh = half(w*s1), biasqkv = w @ shift ---------------
__global__ void prep_w(const float* __restrict__ w_qkv) {
    int gw   = (blockIdx.x * blockDim.x + threadIdx.x) >> 5;   // 768 warps
    int lane = threadIdx.x & 31;
    if (gw >= 2 * QKV_M) return;
    int b = gw / QKV_M, o = gw % QKV_M;
    const float* wr = w_qkv + (size_t)o * CDIM;
    const float* s1 = g_s1 + b * CDIM;
    const float* sh = g_shift + b * CDIM;
    __half* dst = g_wqh + ((size_t)b * QKV_M + o) * CDIM;
    int c0 = lane * 8;
    float4 wa = *(const float4*)(wr + c0), wb = *(const float4*)(wr + c0 + 4);
    float4 sa = *(const float4*)(s1 + c0), sb = *(const float4*)(s1 + c0 + 4);
    float4 ha = *(const float4*)(sh + c0), hb = *(const float4*)(sh + c0 + 4);
    float s = wa.x * ha.x + wa.y * ha.y + wa.z * ha.z + wa.w * ha.w
            + wb.x * hb.x + wb.y * hb.y + wb.z * hb.z + wb.w * hb.w;
    uint4 u;
    u.x = packh2(wa.x * sa.x, wa.y * sa.y);
    u.y = packh2(wa.z * sa.z, wa.w * sa.w);
    u.z = packh2(wb.x * sb.x, wb.y * sb.y);
    u.w = packh2(wb.z * sb.z, wb.w * sb.w);
    *(uint4*)(dst + c0) = u;
#pragma unroll
    for (int off = 16; off; off >>= 1) s += __shfl_xor_sync(FULLMASK, s, off);
    if (lane == 0) g_biasqkv[b * QKV_M + o] = s;
}

// ---------------- 2b) w_out -> half -------------------------------------------
__global__ void conv_woh(const float* __restrict__ w_out) {
    int i = blockIdx.x * blockDim.x + threadIdx.x;   // 4096 threads x 8 elems
    if (i >= CDIM * HID / 8) return;
    const float4* s = (const float4*)w_out;
    float4 a = s[i * 2], c = s[i * 2 + 1];
    uint4 u;
    u.x = packh2(a.x, a.y);  u.y = packh2(a.z, a.w);
    u.z = packh2(c.x, c.y);  u.w = packh2(c.z, c.w);
    ((uint4*)g_woh)[i] = u;
}

// ---------------- 2c) x -> half, transposed to [b][n][c] -----------------------
__global__ void xh_conv(const float* __restrict__ x) {
    __shared__ float t[32][33];
    int b = blockIdx.z, c0 = blockIdx.y * 32, n0 = blockIdx.x * 32;
    int tx = threadIdx.x & 31, ty = threadIdx.x >> 5;
    const float* xb = x + ((size_t)b * CDIM + c0) * N_TOK + n0;
#pragma unroll
    for (int i = 0; i < 4; i++) t[ty + 8 * i][tx] = xb[(size_t)(ty + 8 * i) * N_TOK + tx];
    __syncthreads();
    __half* dst = g_xh + ((size_t)b * N_TOK + n0) * CDIM + c0;
#pragma unroll
    for (int i = 0; i < 4; i++)
        dst[(size_t)(ty + 8 * i) * CDIM + tx] = __float2half(t[tx][ty + 8 * i]);
}

// ---------------- 3) QKV GEMM: f16 mma, epilogue scatters q/k/v ----------------
// Block: 64 o x 128 n, 8 warps. A = g_wqh[b][o][c], B = g_xh[b][n][c].
__global__ __launch_bounds__(256) void qkv_mma() {
    __shared__ __align__(16) char smraw[33792];   // frag 12KB | epi 64x132 f32
    uint2* frag = (uint2*)smraw;
    float* smC  = (float*)smraw;
    __shared__ float biasS[64];

    const int tid = threadIdx.x, lane = tid & 31, wid = tid >> 5;
    const int g = lane >> 2, t = lane & 3;
    const int b = blockIdx.z, o0 = blockIdx.y * 64, n0 = blockIdx.x * 128;

    const __half* A = g_wqh + ((size_t)b * QKV_M + o0) * CDIM;
    const __half* B = g_xh + ((size_t)b * N_TOK + n0) * CDIM;

    const __half* src = nullptr;
    uint32_t dsti = 0;
    bool active = tid < 192;
    if (tid < 64) {
        int r = tid;
        src = A + (size_t)r * CDIM;
        dsti = ((r >> 4) * 2 + ((r & 15) >> 3)) * 32 + (r & 7) * 4;
    } else if (tid < 192) {
        int n = tid - 64;
        src = B + (size_t)n * CDIM;
        dsti = 256 + (n >> 3) * 32 + (n & 7) * 4;
    }
    uint4 lo, hi;
    if (active) { lo = *(const uint4*)src; hi = *(const uint4*)(src + 8); }

    float acc[8][4] = {};
    const int mrow = wid & 3, nhalf = wid >> 2;

    for (int kc = 0; kc < 16; kc++) {
        uint2* buf = frag + (kc & 1) * 768;
        if (active) {
            uint4* dp = (uint4*)(buf + dsti);
            dp[0] = make_uint4(lo.x, hi.x, lo.y, hi.y);
            dp[1] = make_uint4(lo.z, hi.z, lo.w, hi.w);
        }
        __syncthreads();
        if (active && kc < 15) {
            src += 16;
            lo = *(const uint4*)src; hi = *(const uint4*)(src + 8);
        }
        uint2 a02 = buf[(mrow * 2 + 0) * 32 + lane];
        uint2 a13 = buf[(mrow * 2 + 1) * 32 + lane];
#pragma unroll
        for (int j = 0; j < 8; j++) {
            uint2 bb = buf[256 + (nhalf * 8 + j) * 32 + lane];
            mma16(acc[j], a02.x, a13.x, a02.y, a13.y, bb.x, bb.y);
        }
    }
    __syncthreads();   // frag -> smC alias

    float* rowp = smC + (mrow * 16 + g) * 132 + nhalf * 64 + 2 * t;
#pragma unroll
    for (int j = 0; j < 8; j++) {
        rowp[j * 8]             = acc[j][0];
        rowp[j * 8 + 1]         = acc[j][1];
        rowp[8 * 132 + j * 8]     = acc[j][2];
        rowp[8 * 132 + j * 8 + 1] = acc[j][3];
    }
    if (tid < 64) biasS[tid] = g_biasqkv[b * QKV_M + o0 + tid];
    __syncthreads();

    const int kind  = o0 >> 7;            // 0=q,1=k,2=v (uniform per block)
    const int hbase = (o0 >> 5) & 3;
    if (kind < 2) {
        __half* dst = (kind == 0) ? g_q : g_k;
        float sc = (kind == 0) ? QSCALE : 1.f;
#pragma unroll
        for (int i = 0; i < 16; i++) {
            int idx = tid + i * 256;
            int dp = idx & 31, n = idx >> 5;
            int hh = dp >> 4, dpp = dp & 15;
            int r = hh * 32 + dpp * 2;
            float v0 = (smC[r * 132 + n] + biasS[r]) * sc;
            float v1 = (smC[(r + 1) * 132 + n] + biasS[r + 1]) * sc;
            int h = hbase + hh;
            *(uint32_t*)(dst + ((size_t)(b * NHEADS + h) * N_TOK + n0 + n) * DHEAD + dpp * 2)
                = packh2(v0, v1);
        }
    } else {
#pragma unroll
        for (int i = 0; i < 16; i++) {
            int idx = tid + i * 256;
            int np = idx & 63, r = idx >> 6;
            int n = np * 2;
            float bias = biasS[r];
            float v0 = smC[r * 132 + n] + bias;
            float v1 = smC[r * 132 + n + 1] + bias;
            int o = o0 + r, h = (o >> 5) & 3, d = o & 31;
            *(uint32_t*)(g_v + ((size_t)(b * NHEADS + h) * DHEAD + d) * N_TOK + n0 + n)
                = packh2(v0, v1);
        }
    }
}

// ---------------- 4) f16 flash attention, software-pipelined -------------------
__global__ __launch_bounds__(256) void flash_mma() {
    __shared__ __align__(16) uint2 frag[2048];   // 2 x (K 512 | V 512) uint2

    const int tid  = threadIdx.x;
    const int lane = tid & 31, wid = tid >> 5;
    const int g    = lane >> 2, tig = lane & 3;
    const int bh   = blockIdx.y;
    const int q0   = blockIdx.x * 128;

    const __half* Qg = g_q + (size_t)bh * N_TOK * DHEAD;
    const __half* Kg = g_k + (size_t)bh * N_TOK * DHEAD;
    const __half* Vg = g_v + (size_t)bh * DHEAD * N_TOK;

    // staging role + tile-0 prefetch
    const __half* src;
    uint32_t dsti;
    int stride;
    if (tid < 128) {
        int key = tid >> 1, kk = tid & 1;
        src = Kg + (size_t)key * DHEAD + kk * 16;
        stride = 64 * DHEAD;
        dsti = ((key >> 3) * 2 + kk) * 32 + (key & 7) * 4;
    } else {
        int u = tid - 128;
        int d = u >> 2, kk = u & 3;
        src = Vg + (size_t)d * N_TOK + kk * 16;
        stride = 64;
        dsti = 512 + ((d >> 3) * 4 + kk) * 32 + (d & 7) * 4;
    }
    uint4 lo = *(const uint4*)src, hi = *(const uint4*)(src + 8);

    // Q A-fragments (held for whole kernel)
    uint32_t qa[2][4];
    const int qrow = q0 + wid * 16 + g;
#pragma unroll
    for (int kk = 0; kk < 2; kk++) {
        const __half* base = Qg + (size_t)qrow * DHEAD + kk * 16 + 2 * tig;
        qa[kk][0] = *(const uint32_t*)(base);
        qa[kk][1] = *(const uint32_t*)(base + 8 * DHEAD);
        qa[kk][2] = *(const uint32_t*)(base + 8);
        qa[kk][3] = *(const uint32_t*)(base + 8 * DHEAD + 8);
    }

    float o[4][4] = {};
    float m0 = -1e30f, m1 = -1e30f, l0 = 0.f, l1 = 0.f;

    for (int kt = 0; kt < 64; kt++) {
        uint2* buf  = frag + (kt & 1) * 1024;
        uint2* kbuf = buf;
        uint2* vbuf = buf + 512;

        // commit prefetched tile to smem
        {
            uint4* dp = (uint4*)(buf + dsti);
            dp[0] = make_uint4(lo.x, hi.x, lo.y, hi.y);
            dp[1] = make_uint4(lo.z, hi.z, lo.w, hi.w);
        }
        __syncthreads();
        // prefetch next tile (overlaps with compute below)
        if (kt < 63) {
            src += stride;
            lo = *(const uint4*)src;
            hi = *(const uint4*)(src + 8);
        }

        // ---- S = Q @ K^T ----
        float s[8][4];
#pragma unroll
        for (int j = 0; j < 8; j++) {
            s[j][0] = 0.f; s[j][1] = 0.f; s[j][2] = 0.f; s[j][3] = 0.f;
#pragma unroll
            for (int kk = 0; kk < 2; kk++) {
                uint2 b = kbuf[(j * 2 + kk) * 32 + lane];
                mma16(s[j], qa[kk][0], qa[kk][1], qa[kk][2], qa[kk][3], b.x, b.y);
            }
        }

        // ---- online softmax ----
        float mx0 = -1e30f, mx1 = -1e30f;
#pragma unroll
        for (int j = 0; j < 8; j++) {
            mx0 = fmaxf(mx0, fmaxf(s[j][0], s[j][1]));
            mx1 = fmaxf(mx1, fmaxf(s[j][2], s[j][3]));
        }
        mx0 = fmaxf(mx0, __shfl_xor_sync(FULLMASK, mx0, 1));
        mx0 = fmaxf(mx0, __shfl_xor_sync(FULLMASK, mx0, 2));
        mx1 = fmaxf(mx1, __shfl_xor_sync(FULLMASK, mx1, 1));
        mx1 = fmaxf(mx1, __shfl_xor_sync(FULLMASK, mx1, 2));
        float mn0 = fmaxf(m0, mx0), mn1 = fmaxf(m1, mx1);
        float corr0 = __expf(m0 - mn0), corr1 = __expf(m1 - mn1);
        float rs0 = 0.f, rs1 = 0.f;
#pragma unroll
        for (int j = 0; j < 8; j++) {
            s[j][0] = __expf(s[j][0] - mn0);
            s[j][1] = __expf(s[j][1] - mn0);
            s[j][2] = __expf(s[j][2] - mn1);
            s[j][3] = __expf(s[j][3] - mn1);
            rs0 += s[j][0] + s[j][1];
            rs1 += s[j][2] + s[j][3];
        }
        rs0 += __shfl_xor_sync(FULLMASK, rs0, 1);
        rs0 += __shfl_xor_sync(FULLMASK, rs0, 2);
        rs1 += __shfl_xor_sync(FULLMASK, rs1, 1);
        rs1 += __shfl_xor_sync(FULLMASK, rs1, 2);
        l0 = l0 * corr0 + rs0;  m0 = mn0;
        l1 = l1 * corr1 + rs1;  m1 = mn1;

#pragma unroll
        for (int n = 0; n < 4; n++) {
            o[n][0] *= corr0; o[n][1] *= corr0;
            o[n][2] *= corr1; o[n][3] *= corr1;
        }

        // ---- O += P @ V (S C-frag == P A-frag after f16 pack) ----
#pragma unroll
        for (int kk = 0; kk < 4; kk++) {
            uint32_t a0 = packh2(s[2 * kk][0],     s[2 * kk][1]);
            uint32_t a1 = packh2(s[2 * kk][2],     s[2 * kk][3]);
            uint32_t a2 = packh2(s[2 * kk + 1][0], s[2 * kk + 1][1]);
            uint32_t a3 = packh2(s[2 * kk + 1][2], s[2 * kk + 1][3]);
#pragma unroll
            for (int n = 0; n < 4; n++) {
                uint2 b = vbuf[(n * 4 + kk) * 32 + lane];
                mma16(o[n], a0, a1, a2, a3, b.x, b.y);
            }
        }
    }

    // ---- epilogue: direct half2 stores to g_aoh[b][n][h*32+d] ----
    const int b = bh >> 2, h = bh & 3;
    float inv0 = 1.f / l0, inv1 = 1.f / l1;
    __half* ao0 = g_aoh + ((size_t)b * N_TOK + qrow) * HID + h * 32;
    __half* ao1 = ao0 + 8 * HID;
#pragma unroll
    for (int n = 0; n < 4; n++) {
        int d0 = n * 8 + 2 * tig;
        *(uint32_t*)(ao0 + d0) = packh2(o[n][0] * inv0, o[n][1] * inv0);
        *(uint32_t*)(ao1 + d0) = packh2(o[n][2] * inv1, o[n][3] * inv1);
    }
}

// ---------------- 5) output projection: f16 mma --------------------------------
// Block: 64 o x 128 n. A = g_woh[o][k], B = g_aoh[b][n][k], K=128.
__global__ __launch_bounds__(256) void out_mma(const float* __restrict__ b_out,
                                               float* __restrict__ out) {
    __shared__ __align__(16) uint2 frag[2 * 768];

    const int tid = threadIdx.x, lane = tid & 31, wid = tid >> 5;
    const int g = lane >> 2, t = lane & 3;
    const int b = blockIdx.z, o0 = blockIdx.y * 64, n0 = blockIdx.x * 128;

    const __half* A = g_woh + (size_t)o0 * HID;
    const __half* B = g_aoh + ((size_t)b * N_TOK + n0) * HID;

    const __half* src = nullptr;
    uint32_t dsti = 0;
    bool active = tid < 192;
    if (tid < 64) {
        int r = tid;
        src = A + (size_t)r * HID;
        dsti = ((r >> 4) * 2 + ((r & 15) >> 3)) * 32 + (r & 7) * 4;
    } else if (tid < 192) {
        int n = tid - 64;
        src = B + (size_t)n * HID;
        dsti = 256 + (n >> 3) * 32 + (n & 7) * 4;
    }
    uint4 lo, hi;
    if (active) { lo = *(const uint4*)src; hi = *(const uint4*)(src + 8); }

    float acc[8][4] = {};
    const int mrow = wid & 3, nhalf = wid >> 2;

    for (int kc = 0; kc < 8; kc++) {
        uint2* buf = frag + (kc & 1) * 768;
        if (active) {
            uint4* dp = (uint4*)(buf + dsti);
            dp[0] = make_uint4(lo.x, hi.x, lo.y, hi.y);
            dp[1] = make_uint4(lo.z, hi.z, lo.w, hi.w);
        }
        __syncthreads();
        if (active && kc < 7) {
            src += 16;
            lo = *(const uint4*)src; hi = *(const uint4*)(src + 8);
        }
        uint2 a02 = buf[(mrow * 2 + 0) * 32 + lane];
        uint2 a13 = buf[(mrow * 2 + 1) * 32 + lane];
#pragma unroll
        for (int j = 0; j < 8; j++) {
            uint2 bb = buf[256 + (nhalf * 8 + j) * 32 + lane];
            mma16(acc[j], a02.x, a13.x, a02.y, a13.y, bb.x, bb.y);
        }
    }

    // epilogue: direct float2 stores + bias
    const int orow = o0 + mrow * 16 + g;
    const float bias0 = b_out[orow], bias1 = b_out[orow + 8];
    float* dst0 = out + ((size_t)b * CDIM + orow) * N_TOK + n0 + nhalf * 64 + 2 * t;
    float* dst1 = dst0 + 8 * N_TOK;
#pragma unroll
    for (int j = 0; j < 8; j++) {
        *(float2*)(dst0 + j * 8) = make_float2(acc[j][0] + bias0, acc[j][1] + bias0);
        *(float2*)(dst1 + j * 8) = make_float2(acc[j][2] + bias1, acc[j][3] + bias1);
    }
}

// ---------------- launch -------------------------------------------------------
extern "C" void kernel_launch(void* const* d_in, const int* in_sizes, int n_in,
                              void* d_out, int out_size) {
    const float* x      = (const float*)d_in[0];
    const float* te     = (const float*)d_in[1];
    const float* w_mlp  = (const float*)d_in[2];
    const float* b_mlp  = (const float*)d_in[3];
    const float* w_qkv  = (const float*)d_in[4];
    const float* w_out  = (const float*)d_in[5];
    const float* b_out  = (const float*)d_in[6];
    float* out = (float*)d_out;

    film_kernel<<<128, 256>>>(te, w_mlp, b_mlp);
    conv_woh<<<16, 256>>>(w_out);
    xh_conv<<<dim3(128, 8, 2), 256>>>(x);
    prep_w<<<96, 256>>>(w_qkv);
    qkv_mma<<<dim3(32, 6, 2), 256>>>();
    flash_mma<<<dim3(32, 8), 256>>>();
    out_mma<<<dim3(32, 4, 2), 256>>>(b_out, out);
}